// round 12
// baseline (speedup 1.0000x reference)
#include <cuda_runtime.h>
#include <cuda_bf16.h>
#include <cstdint>

#define NV 2048
#define NE 8192
#define D  128

// ---------------- device scratch (static: no runtime allocation) ----------------
__device__ __align__(16) float g_w[NE];                            // 32 KB
__device__ __align__(16) __nv_bfloat16 g_Ah[(size_t)NV * NE];      // 32 MB  hi(T*w)
__device__ __align__(16) __nv_bfloat16 g_Al[(size_t)NV * NE];      // 32 MB  lo(T*w)
__device__ __align__(16) __nv_bfloat16 g_Bh[(size_t)NV * NE];      // 32 MB  hi(T)
__device__ __align__(16) __nv_bfloat16 g_Bl[(size_t)NV * NE];      // 32 MB  lo(T)
__device__ __align__(16) float g_adjA[(size_t)NV * NV];            // 16 MB
__device__ __align__(16) float g_HW[NV * D];                       // 1 MB

// ---------------- helpers ----------------
__device__ __forceinline__ void mma_bf16(float* d, const uint32_t* a, const uint32_t* b) {
    asm volatile(
        "mma.sync.aligned.m16n8k16.row.col.f32.bf16.bf16.f32 "
        "{%0,%1,%2,%3}, {%4,%5,%6,%7}, {%8,%9}, {%0,%1,%2,%3};\n"
        : "+f"(d[0]), "+f"(d[1]), "+f"(d[2]), "+f"(d[3])
        : "r"(a[0]), "r"(a[1]), "r"(a[2]), "r"(a[3]), "r"(b[0]), "r"(b[1]));
}

__device__ __forceinline__ void ldsm4(uint32_t* r, uint32_t saddr) {
    asm volatile("ldmatrix.sync.aligned.m8n8.x4.shared.b16 {%0,%1,%2,%3}, [%4];"
                 : "=r"(r[0]), "=r"(r[1]), "=r"(r[2]), "=r"(r[3]) : "r"(saddr));
}

__device__ __forceinline__ void cp_async16(uint32_t saddr, const void* g) {
    asm volatile("cp.async.cg.shared.global [%0], [%1], 16;\n" :: "r"(saddr), "l"(g));
}
__device__ __forceinline__ void cp_commit() { asm volatile("cp.async.commit_group;\n" ::: "memory"); }
__device__ __forceinline__ void cp_wait1()  { asm volatile("cp.async.wait_group 1;\n" ::: "memory"); }
__device__ __forceinline__ void cp_wait0()  { asm volatile("cp.async.wait_group 0;\n" ::: "memory"); }

__device__ __forceinline__ uint32_t smem_u32(const void* p) {
    uint32_t a;
    asm("{ .reg .u64 t; cvta.to.shared.u64 t, %1; cvt.u32.u64 %0, t; }" : "=r"(a) : "l"(p));
    return a;
}

__device__ __forceinline__ void gbar(int id) {
    asm volatile("bar.sync %0, %1;" :: "r"(id), "r"(256) : "memory");
}

__device__ __forceinline__ uint32_t pkbf(__nv_bfloat16 a, __nv_bfloat16 b) {
    return (uint32_t)__bfloat16_as_ushort(a) | ((uint32_t)__bfloat16_as_ushort(b) << 16);
}

// ---------------- kernel 1: w = H_e @ p  (warp per row) ----------------
__global__ void k_w(const float* __restrict__ He, const float* __restrict__ p) {
    int row  = blockIdx.x * 8 + (threadIdx.x >> 5);
    int lane = threadIdx.x & 31;
    const float* r = He + (size_t)row * D;
    float s = 0.f;
#pragma unroll
    for (int j = 0; j < 4; j++) {
        int k = lane + 32 * j;
        s += r[k] * __ldg(p + k);
    }
#pragma unroll
    for (int o = 16; o > 0; o >>= 1) s += __shfl_xor_sync(0xffffffffu, s, o);
    if (lane == 0) g_w[row] = s;
}

// ---------------- kernel 2: split planes. A=T*w (fp32, full precision), B=T ----------------
__global__ void __launch_bounds__(256)
k_prep(const float* __restrict__ T) {
    const size_t stride = (size_t)gridDim.x * blockDim.x;   // 524288
    size_t c = (size_t)blockIdx.x * blockDim.x + threadIdx.x;
#pragma unroll
    for (int it = 0; it < 8; it++, c += stride) {
        size_t e  = c * 4;
        int col = (int)(e & (size_t)(NE - 1));
        float4 t = *reinterpret_cast<const float4*>(T + e);
        float4 w = *reinterpret_cast<const float4*>(g_w + col);
        float a[4] = {t.x * w.x, t.y * w.y, t.z * w.z, t.w * w.w};
        float b[4] = {t.x, t.y, t.z, t.w};
        __nv_bfloat16 ah[4], al[4], bh[4], bl[4];
#pragma unroll
        for (int q = 0; q < 4; q++) {
            ah[q] = __float2bfloat16_rn(a[q]);
            al[q] = __float2bfloat16_rn(a[q] - __bfloat162float(ah[q]));
            bh[q] = __float2bfloat16_rn(b[q]);
            bl[q] = __float2bfloat16_rn(b[q] - __bfloat162float(bh[q]));
        }
        *reinterpret_cast<uint2*>(g_Ah + e) = make_uint2(pkbf(ah[0], ah[1]), pkbf(ah[2], ah[3]));
        *reinterpret_cast<uint2*>(g_Al + e) = make_uint2(pkbf(al[0], al[1]), pkbf(al[2], al[3]));
        *reinterpret_cast<uint2*>(g_Bh + e) = make_uint2(pkbf(bh[0], bh[1]), pkbf(bh[2], bh[3]));
        *reinterpret_cast<uint2*>(g_Bl + e) = make_uint2(pkbf(bl[0], bl[1]), pkbf(bl[2], bl[3]));
    }
}

// ---------------- kernel 3: HW = H_v @ weight  (8 rows per block) ----------------
__global__ void k_hw(const float* __restrict__ Hv, const float* __restrict__ W) {
    __shared__ float sh[8][D];
    int r0  = blockIdx.x * 8;
    int tid = threadIdx.x;  // 128
#pragma unroll
    for (int r = 0; r < 8; r++) sh[r][tid] = Hv[(size_t)(r0 + r) * D + tid];
    __syncthreads();
    float acc[8] = {};
    for (int k = 0; k < D; k++) {
        float wk = W[k * D + tid];
#pragma unroll
        for (int r = 0; r < 8; r++) acc[r] += sh[r][k] * wk;
    }
#pragma unroll
    for (int r = 0; r < 8; r++) g_HW[(r0 + r) * D + tid] = acc[r];
}

// ---------------- kernel 4: symmetric GEMM, bf16 split (hi/lo), 2 pipelines ----
// C = (T*w) @ T^T via 3 bf16 MMAs per k16 (hihi + hilo + lohi), fp32 accum.
// Two 8-warp groups, each K-half with own cp.async ring + named barriers.
// SMEM tile row = 128B: [hi 64B | lo 64B], SW128 XOR swizzle, conflict-free.
#define BM 128
#define BK 32
#define STAGE_BYTES 32768                 // A tile 16KB + B tile 16KB
#define NSTAGE 3
#define GROUP_BYTES (NSTAGE * STAGE_BYTES)       // 98304
#define SMEM_BYTES (2 * GROUP_BYTES)             // 196608
#define CSTRIDE 132

__global__ void __launch_bounds__(512, 1)
k_gemm1(const float* __restrict__ adj_v) {
    // decode upper-triangular block index (16x16 grid of 128-blocks)
    int l = blockIdx.x, bm = 0, rem = 16;
    while (l >= rem) { l -= rem; bm++; rem--; }
    int bn = bm + l;

    extern __shared__ float smem[];
    uint32_t sbase = smem_u32(smem);

    int tid  = threadIdx.x;
    int warp = tid >> 5, lane = tid & 31;
    int grp  = warp >> 3;                  // 0/1: K-half + pipeline id
    int gtid = tid & 255;
    int w8   = warp & 7;
    int wm = w8 & 3, wn = w8 >> 2;         // 4x2 grid: warp = 32 rows x 64 cols
    int gid = lane >> 2, tig = lane & 3;

    size_t rowOffA = (size_t)(bm * BM) * NE + grp * (NE / 2);
    size_t rowOffB = (size_t)(bn * BM) * NE + grp * (NE / 2);
    uint32_t gbase = sbase + (uint32_t)grp * GROUP_BYTES;
    int bar = grp + 1;

    float acc[2][8][4];
#pragma unroll
    for (int m = 0; m < 2; m++)
#pragma unroll
        for (int n = 0; n < 8; n++)
#pragma unroll
            for (int q = 0; q < 4; q++) acc[m][n][q] = 0.f;

    const int nkt = (NE / 2) / BK;  // 128 iterations per group

    // stage loader: 2048 16B-chunks over 256 threads (8 each)
    // chunk sub-coords fixed per thread: sub = gtid&7 -> plane=sub>>2, cc=sub&3
    int sub  = gtid & 7, plane = sub >> 2, cc = sub & 3;
    const __nv_bfloat16* arrA = plane ? g_Al : g_Ah;
    const __nv_bfloat16* arrB = plane ? g_Bl : g_Bh;
    auto load_stage = [&](int s, int kt) {
        uint32_t base = gbase + (uint32_t)s * STAGE_BYTES;
#pragma unroll
        for (int i = 0; i < 8; i++) {
            int c = i * 256 + gtid;
            int operand = c >> 10;
            int row = (c & 1023) >> 3;
            uint32_t off = (uint32_t)(operand * 16384 + row * 128 + plane * 64 + cc * 16);
            uint32_t sw  = off ^ ((off >> 3) & 0x70);
            const __nv_bfloat16* src =
                (operand ? arrB + rowOffB : arrA + rowOffA)
                + (size_t)row * NE + kt * BK + cc * 8;
            cp_async16(base + sw, src);
        }
        cp_commit();
    };

    load_stage(0, 0);
    load_stage(1, 1);

    // LDSM address bases (bytes within a stage); +ks*32 then ^xmask at use
    uint32_t xmask = (uint32_t)(lane & 7) << 4;
    uint32_t aoff[2][2], boff[4][2];
#pragma unroll
    for (int m = 0; m < 2; m++) {
        int rowA = wm * 32 + m * 16 + ((lane >> 3) & 1) * 8 + (lane & 7);
#pragma unroll
        for (int p = 0; p < 2; p++)
            aoff[m][p] = (uint32_t)(rowA * 128 + p * 64 + ((lane >> 4) & 1) * 16);
    }
#pragma unroll
    for (int j = 0; j < 4; j++) {
        int rowB = wn * 64 + j * 16 + ((lane >> 4) & 1) * 8 + (lane & 7);
#pragma unroll
        for (int p = 0; p < 2; p++)
            boff[j][p] = (uint32_t)(16384 + rowB * 128 + p * 64 + ((lane >> 3) & 1) * 16);
    }

    for (int kt = 0; kt < nkt; kt++) {
        if (kt + 1 < nkt) cp_wait1(); else cp_wait0();
        gbar(bar);
        int s = kt % NSTAGE;
        if (kt + 2 < nkt) load_stage((kt + 2) % NSTAGE, kt + 2);

        uint32_t stb = gbase + (uint32_t)s * STAGE_BYTES;

#pragma unroll
        for (int ks = 0; ks < 2; ks++) {         // two k16 steps per BK=32
            uint32_t af[2][2][4];                 // [m][plane]
#pragma unroll
            for (int m = 0; m < 2; m++)
#pragma unroll
                for (int p = 0; p < 2; p++)
                    ldsm4(af[m][p], stb + ((aoff[m][p] + ks * 32) ^ xmask));

#pragma unroll
            for (int h = 0; h < 2; h++) {        // n-halves: regs stay bounded
                uint32_t bq[2][2][4];             // [j-local][plane]
#pragma unroll
                for (int j = 0; j < 2; j++)
#pragma unroll
                    for (int p = 0; p < 2; p++)
                        ldsm4(bq[j][p], stb + ((boff[2 * h + j][p] + ks * 32) ^ xmask));
#pragma unroll
                for (int m = 0; m < 2; m++)
#pragma unroll
                    for (int nt = 0; nt < 4; nt++) {
                        int n = 4 * h + nt;
                        const uint32_t* bhv = &bq[nt >> 1][0][(nt & 1) * 2];
                        const uint32_t* blv = &bq[nt >> 1][1][(nt & 1) * 2];
                        mma_bf16(acc[m][n], af[m][0], bhv);  // hi*hi
                        mma_bf16(acc[m][n], af[m][0], blv);  // hi*lo
                        mma_bf16(acc[m][n], af[m][1], bhv);  // lo*hi
                    }
            }
        }
    }

    // ---- combine group partials through smem (group 1's area), then epilogue ----
    __syncthreads();
    float* cbuf = smem + GROUP_BYTES / 4;   // 128 x CSTRIDE floats = 67.6 KB, fits
    if (grp == 1) {
#pragma unroll
        for (int m = 0; m < 2; m++) {
            int il = wm * 32 + m * 16 + gid;
#pragma unroll
            for (int n = 0; n < 8; n++) {
                int jl = wn * 64 + n * 8 + 2 * tig;
#pragma unroll
                for (int q = 0; q < 4; q++)
                    cbuf[(il + (q >> 1) * 8) * CSTRIDE + jl + (q & 1)] = acc[m][n][q];
            }
        }
    }
    __syncthreads();

    if (grp == 0) {
        bool offdiag = (bm != bn);
#pragma unroll
        for (int m = 0; m < 2; m++) {
            int il0 = wm * 32 + m * 16 + gid;
#pragma unroll
            for (int n = 0; n < 8; n++) {
                int jl0 = wn * 64 + n * 8 + 2 * tig;
#pragma unroll
                for (int q = 0; q < 4; q++) {
                    int il = il0 + (q >> 1) * 8;
                    int jl = jl0 + (q & 1);
                    int i = bm * BM + il;
                    int j = bn * BM + jl;
                    float v = acc[m][n][q] + cbuf[il * CSTRIDE + jl];
                    float m1 = (i == j) ? 1.0f : v;
                    g_adjA[(size_t)i * NV + j] = m1 * adj_v[(size_t)i * NV + j];
                    if (offdiag)  // i != j guaranteed
                        g_adjA[(size_t)j * NV + i] = v * adj_v[(size_t)j * NV + i];
                }
            }
        }
    }
}

// ---------------- kernel 5: ret = adjA @ HW + bias (pipelined fp32 SIMT) ----------------
#define BK2 32
#define H_FLOATS (BK2 * D)           // 4096 floats (HW tile)
#define A_STRIDE 36
#define A_FLOATS (16 * A_STRIDE)     // 576 floats
#define STG2_FLOATS (H_FLOATS + A_FLOATS)   // 4672
#define NSTG2 3
#define SMEM2_BYTES (NSTG2 * STG2_FLOATS * 4)  // 56064 B

__global__ void __launch_bounds__(256, 1)
k_gemm2(const float* __restrict__ bias, float* __restrict__ out) {
    extern __shared__ float sm2[];
    uint32_t sb = smem_u32(sm2);

    int tid  = threadIdx.x;
    int warp = tid >> 5, lane = tid & 31;
    int colb = (warp & 3) * 32 + (lane & 7) * 4;
    int rowb = (warp >> 2) * 8 + (lane >> 3) * 2;
    int r0   = blockIdx.x * 16;

    const int nkt = NV / BK2;  // 64

    auto load_stage = [&](int s, int kt) {
        uint32_t base = sb + (uint32_t)(s * STG2_FLOATS) * 4u;
#pragma unroll
        for (int i = 0; i < 4; i++) {
            int c = i * 256 + tid;
            int row = c >> 5, cic = c & 31;
            cp_async16(base + (uint32_t)(row * D + cic * 4) * 4u,
                       g_HW + (size_t)(kt * BK2 + row) * D + cic * 4);
        }
        if (tid < 128) {
            int row = tid >> 3, cic = tid & 7;
            cp_async16(base + (uint32_t)(H_FLOATS + row * A_STRIDE + cic * 4) * 4u,
                       g_adjA + (size_t)(r0 + row) * NV + kt * BK2 + cic * 4);
        }
        cp_commit();
    };

    load_stage(0, 0);
    load_stage(1, 1);

    float4 acc0 = {0.f, 0.f, 0.f, 0.f};
    float4 acc1 = {0.f, 0.f, 0.f, 0.f};

    for (int kt = 0; kt < nkt; kt++) {
        if (kt + 1 < nkt) cp_wait1(); else cp_wait0();
        __syncthreads();
        int s = kt % NSTG2;
        if (kt + 2 < nkt) load_stage((kt + 2) % NSTG2, kt + 2);

        const float* sH = sm2 + s * STG2_FLOATS;
        const float* sA = sH + H_FLOATS;
        const float* a0p = sA + rowb * A_STRIDE;
        const float* a1p = a0p + A_STRIDE;

#pragma unroll
        for (int k4 = 0; k4 < BK2 / 4; k4++) {
            float4 a0 = *reinterpret_cast<const float4*>(a0p + k4 * 4);
            float4 a1 = *reinterpret_cast<const float4*>(a1p + k4 * 4);
#pragma unroll
            for (int kk = 0; kk < 4; kk++) {
                float4 h = *reinterpret_cast<const float4*>(sH + (k4 * 4 + kk) * D + colb);
                float av0 = (kk == 0) ? a0.x : (kk == 1) ? a0.y : (kk == 2) ? a0.z : a0.w;
                float av1 = (kk == 0) ? a1.x : (kk == 1) ? a1.y : (kk == 2) ? a1.z : a1.w;
                acc0.x += av0 * h.x; acc0.y += av0 * h.y;
                acc0.z += av0 * h.z; acc0.w += av0 * h.w;
                acc1.x += av1 * h.x; acc1.y += av1 * h.y;
                acc1.z += av1 * h.z; acc1.w += av1 * h.w;
            }
        }
    }

    float4 b = *reinterpret_cast<const float4*>(bias + colb);
    acc0.x += b.x; acc0.y += b.y; acc0.z += b.z; acc0.w += b.w;
    acc1.x += b.x; acc1.y += b.y; acc1.z += b.z; acc1.w += b.w;
    *reinterpret_cast<float4*>(out + (size_t)(r0 + rowb) * D + colb)     = acc0;
    *reinterpret_cast<float4*>(out + (size_t)(r0 + rowb + 1) * D + colb) = acc1;
}

// ---------------- launch ----------------
extern "C" void kernel_launch(void* const* d_in, const int* in_sizes, int n_in,
                              void* d_out, int out_size) {
    const float* H_v   = (const float*)d_in[0];
    const float* H_e   = (const float*)d_in[1];
    // d_in[2] = adj_e : UNUSED by the reference graph (node_layer branch)
    const float* adj_v = (const float*)d_in[3];
    const float* T     = (const float*)d_in[4];
    const float* W     = (const float*)d_in[5];
    const float* p     = (const float*)d_in[6];
    const float* bias  = (const float*)d_in[7];
    float* out = (float*)d_out;

    k_w<<<NE / 8, 256>>>(H_e, p);
    k_prep<<<2048, 256>>>(T);
    k_hw<<<NV / 8, 128>>>(H_v, W);

    cudaFuncSetAttribute(k_gemm1, cudaFuncAttributeMaxDynamicSharedMemorySize, SMEM_BYTES);
    k_gemm1<<<136, 512, SMEM_BYTES>>>(adj_v);

    cudaFuncSetAttribute(k_gemm2, cudaFuncAttributeMaxDynamicSharedMemorySize, SMEM2_BYTES);
    k_gemm2<<<NV / 16, 256, SMEM2_BYTES>>>(bias, out);

    // second output: H_e passthrough, concatenated after ret
    if (out_size >= NV * D + NE * D) {
        cudaMemcpyAsync(out + NV * D, H_e, (size_t)NE * D * sizeof(float),
                        cudaMemcpyDeviceToDevice, 0);
    }
}

// round 13
// speedup vs baseline: 1.9874x; 1.9874x over previous
#include <cuda_runtime.h>
#include <cuda_fp16.h>
#include <cstdint>

#define NV 2048
#define NE 8192
#define D  128

// ---------------- device scratch (static: no runtime allocation) ----------------
__device__ __align__(16) float g_w[NE];                     // 32 KB
__device__ __align__(16) __half g_A[(size_t)NV * NE];       // 32 MB  fp16(T*w)
__device__ __align__(16) __half g_B[(size_t)NV * NE];       // 32 MB  fp16(T)
__device__ __align__(16) float g_adjA[(size_t)NV * NV];     // 16 MB
__device__ __align__(16) float g_HW[NV * D];                // 1 MB

// ---------------- helpers ----------------
__device__ __forceinline__ void mma_fp16(float* d, const uint32_t* a, const uint32_t* b) {
    asm volatile(
        "mma.sync.aligned.m16n8k16.row.col.f32.f16.f16.f32 "
        "{%0,%1,%2,%3}, {%4,%5,%6,%7}, {%8,%9}, {%0,%1,%2,%3};\n"
        : "+f"(d[0]), "+f"(d[1]), "+f"(d[2]), "+f"(d[3])
        : "r"(a[0]), "r"(a[1]), "r"(a[2]), "r"(a[3]), "r"(b[0]), "r"(b[1]));
}

__device__ __forceinline__ void ldsm4(uint32_t* r, uint32_t saddr) {
    asm volatile("ldmatrix.sync.aligned.m8n8.x4.shared.b16 {%0,%1,%2,%3}, [%4];"
                 : "=r"(r[0]), "=r"(r[1]), "=r"(r[2]), "=r"(r[3]) : "r"(saddr));
}

__device__ __forceinline__ void cp_async16(uint32_t saddr, const void* g) {
    asm volatile("cp.async.cg.shared.global [%0], [%1], 16;\n" :: "r"(saddr), "l"(g));
}
__device__ __forceinline__ void cp_commit() { asm volatile("cp.async.commit_group;\n" ::: "memory"); }
__device__ __forceinline__ void cp_wait1()  { asm volatile("cp.async.wait_group 1;\n" ::: "memory"); }
__device__ __forceinline__ void cp_wait0()  { asm volatile("cp.async.wait_group 0;\n" ::: "memory"); }

__device__ __forceinline__ uint32_t smem_u32(const void* p) {
    uint32_t a;
    asm("{ .reg .u64 t; cvta.to.shared.u64 t, %1; cvt.u32.u64 %0, t; }" : "=r"(a) : "l"(p));
    return a;
}

__device__ __forceinline__ void gbar(int id) {
    asm volatile("bar.sync %0, %1;" :: "r"(id), "r"(256) : "memory");
}

__device__ __forceinline__ uint32_t pkh(__half a, __half b) {
    return (uint32_t)__half_as_ushort(a) | ((uint32_t)__half_as_ushort(b) << 16);
}

// ---------------- kernel 1: w = H_e @ p  (warp per row) ----------------
__global__ void k_w(const float* __restrict__ He, const float* __restrict__ p) {
    int row  = blockIdx.x * 8 + (threadIdx.x >> 5);
    int lane = threadIdx.x & 31;
    const float* r = He + (size_t)row * D;
    float s = 0.f;
#pragma unroll
    for (int j = 0; j < 4; j++) {
        int k = lane + 32 * j;
        s += r[k] * __ldg(p + k);
    }
#pragma unroll
    for (int o = 16; o > 0; o >>= 1) s += __shfl_xor_sync(0xffffffffu, s, o);
    if (lane == 0) g_w[row] = s;
}

// ---------------- kernel 2: A = fp16(T*w), B = fp16(T)  (one read of T) ----------------
__global__ void __launch_bounds__(256)
k_prep(const float* __restrict__ T) {
    const size_t stride = (size_t)gridDim.x * blockDim.x;   // 524288
    size_t c = (size_t)blockIdx.x * blockDim.x + threadIdx.x;
#pragma unroll
    for (int it = 0; it < 8; it++, c += stride) {
        size_t e  = c * 4;
        int col = (int)(e & (size_t)(NE - 1));
        float4 t = *reinterpret_cast<const float4*>(T + e);
        float4 w = *reinterpret_cast<const float4*>(g_w + col);
        __half a0 = __float2half_rn(t.x * w.x), a1 = __float2half_rn(t.y * w.y);
        __half a2 = __float2half_rn(t.z * w.z), a3 = __float2half_rn(t.w * w.w);
        __half b0 = __float2half_rn(t.x), b1 = __float2half_rn(t.y);
        __half b2 = __float2half_rn(t.z), b3 = __float2half_rn(t.w);
        *reinterpret_cast<uint2*>(g_A + e) = make_uint2(pkh(a0, a1), pkh(a2, a3));
        *reinterpret_cast<uint2*>(g_B + e) = make_uint2(pkh(b0, b1), pkh(b2, b3));
    }
}

// ---------------- kernel 3: HW = H_v @ weight  (8 rows per block) ----------------
__global__ void k_hw(const float* __restrict__ Hv, const float* __restrict__ W) {
    __shared__ float sh[8][D];
    int r0  = blockIdx.x * 8;
    int tid = threadIdx.x;  // 128
#pragma unroll
    for (int r = 0; r < 8; r++) sh[r][tid] = Hv[(size_t)(r0 + r) * D + tid];
    __syncthreads();
    float acc[8] = {};
    for (int k = 0; k < D; k++) {
        float wk = W[k * D + tid];
#pragma unroll
        for (int r = 0; r < 8; r++) acc[r] += sh[r][k] * wk;
    }
#pragma unroll
    for (int r = 0; r < 8; r++) g_HW[(r0 + r) * D + tid] = acc[r];
}

// ---------------- kernel 4: symmetric GEMM, fp16 m16n8k16, 2 pipelines ----
// C = fp16(T*w) @ fp16(T)^T  (2048x2048, K=8192), upper-tri 128x128 blocks.
// fp16 mantissa == tf32 mantissa (10 bits) -> same precision, HALF the MMA
// instructions and HALF the fragment bytes of the tf32 path.
// Two 8-warp groups (4x2 grid of 32x64 tiles), each K-half, own cp.async
// ring + named barriers. SMEM row = 64 halfs = 128B, SW128 XOR swizzle.
#define BM 128
#define BK 64                              // 64 halfs = one 128B row
#define TILE_B 16384                       // 128 rows x 128B
#define STAGE_BYTES (2 * TILE_B)           // A + B = 32KB
#define NSTAGE 3
#define GROUP_BYTES (NSTAGE * STAGE_BYTES) // 98304
#define SMEM_BYTES (2 * GROUP_BYTES)       // 196608
#define CSTRIDE 132

__global__ void __launch_bounds__(512, 1)
k_gemm1(const float* __restrict__ adj_v) {
    // decode upper-triangular block index (16x16 grid of 128-blocks)
    int l = blockIdx.x, bm = 0, rem = 16;
    while (l >= rem) { l -= rem; bm++; rem--; }
    int bn = bm + l;

    extern __shared__ float smem[];
    uint32_t sbase = smem_u32(smem);

    int tid  = threadIdx.x;
    int warp = tid >> 5, lane = tid & 31;
    int grp  = warp >> 3;                  // 0/1: K-half + pipeline id
    int gtid = tid & 255;
    int w8   = warp & 7;
    int wm = w8 & 3, wn = w8 >> 2;         // 4x2 grid: warp = 32 rows x 64 cols
    int gid = lane >> 2, tig = lane & 3;

    const __half* gA = g_A + (size_t)(bm * BM) * NE + grp * (NE / 2);
    const __half* gB = g_B + (size_t)(bn * BM) * NE + grp * (NE / 2);
    uint32_t gbase = sbase + (uint32_t)grp * GROUP_BYTES;
    int bar = grp + 1;

    float acc[2][8][4];
#pragma unroll
    for (int m = 0; m < 2; m++)
#pragma unroll
        for (int n = 0; n < 8; n++)
#pragma unroll
            for (int q = 0; q < 4; q++) acc[m][n][q] = 0.f;

    const int nkt = (NE / 2) / BK;  // 32 iterations per group

    // stage loader: 2048 16B-chunks over 256 threads (8 each)
    auto load_stage = [&](int s, int kt) {
        uint32_t base = gbase + (uint32_t)s * STAGE_BYTES;
        int cc = gtid & 7;                      // fixed 16B column per thread
#pragma unroll
        for (int i = 0; i < 8; i++) {
            int c = i * 256 + gtid;
            int operand = c >> 10;              // 0 = A, 1 = B
            int row = (c >> 3) & 127;
            uint32_t off = (uint32_t)(operand * TILE_B + row * 128 + cc * 16);
            uint32_t sw  = off ^ ((off >> 3) & 0x70);
            const __half* src = (operand ? gB : gA)
                              + (size_t)row * NE + kt * BK + cc * 8;
            cp_async16(base + sw, src);
        }
        cp_commit();
    };

    load_stage(0, 0);
    load_stage(1, 1);

    // LDSM base offsets (bytes within stage). row&7 == lane&7 always, so the
    // swizzle reduces to a per-lane XOR mask applied after adding ks*32.
    uint32_t xmask = (uint32_t)(lane & 7) << 4;
    uint32_t aoff[2], boff[4];
#pragma unroll
    for (int m = 0; m < 2; m++) {
        int rowA = wm * 32 + m * 16 + (lane & 7) + ((lane >> 3) & 1) * 8;
        aoff[m] = (uint32_t)(rowA * 128 + ((lane >> 4) & 1) * 16);
    }
#pragma unroll
    for (int j = 0; j < 4; j++) {
        int rowB = wn * 64 + j * 16 + (lane & 7) + ((lane >> 3) & 1) * 8;
        boff[j] = (uint32_t)(TILE_B + rowB * 128 + ((lane >> 4) & 1) * 16);
    }

    for (int kt = 0; kt < nkt; kt++) {
        if (kt + 1 < nkt) cp_wait1(); else cp_wait0();
        gbar(bar);
        int s = kt % NSTAGE;
        if (kt + 2 < nkt) load_stage((kt + 2) % NSTAGE, kt + 2);

        uint32_t stb = gbase + (uint32_t)s * STAGE_BYTES;

#pragma unroll
        for (int ks = 0; ks < 4; ks++) {          // four k16 steps per BK=64
            uint32_t kb = (uint32_t)(ks * 32);
            uint32_t af[2][4], bf[8][2];
#pragma unroll
            for (int m = 0; m < 2; m++)
                ldsm4(af[m], stb + ((aoff[m] + kb) ^ xmask));
#pragma unroll
            for (int j = 0; j < 4; j++) {
                uint32_t r[4];
                ldsm4(r, stb + ((boff[j] + kb) ^ xmask));
                bf[2 * j][0]     = r[0];
                bf[2 * j + 1][0] = r[1];
                bf[2 * j][1]     = r[2];
                bf[2 * j + 1][1] = r[3];
            }
#pragma unroll
            for (int m = 0; m < 2; m++)
#pragma unroll
                for (int n = 0; n < 8; n++) mma_fp16(acc[m][n], af[m], bf[n]);
        }
        gbar(bar);   // protect stage from overwrite until all group warps consumed it
    }

    // ---- combine group partials through smem (group 1's area), then epilogue ----
    __syncthreads();
    float* cbuf = smem + GROUP_BYTES / 4;   // 128 x 132 floats = 67.6 KB, fits
    if (grp == 1) {
#pragma unroll
        for (int m = 0; m < 2; m++) {
            int il = wm * 32 + m * 16 + gid;
#pragma unroll
            for (int n = 0; n < 8; n++) {
                int jl = wn * 64 + n * 8 + 2 * tig;
#pragma unroll
                for (int q = 0; q < 4; q++)
                    cbuf[(il + (q >> 1) * 8) * CSTRIDE + jl + (q & 1)] = acc[m][n][q];
            }
        }
    }
    __syncthreads();

    if (grp == 0) {
        bool offdiag = (bm != bn);
#pragma unroll
        for (int m = 0; m < 2; m++) {
            int il0 = wm * 32 + m * 16 + gid;
#pragma unroll
            for (int n = 0; n < 8; n++) {
                int jl0 = wn * 64 + n * 8 + 2 * tig;
#pragma unroll
                for (int q = 0; q < 4; q++) {
                    int il = il0 + (q >> 1) * 8;
                    int jl = jl0 + (q & 1);
                    int i = bm * BM + il;
                    int j = bn * BM + jl;
                    float v = acc[m][n][q] + cbuf[il * CSTRIDE + jl];
                    float m1 = (i == j) ? 1.0f : v;
                    g_adjA[(size_t)i * NV + j] = m1 * adj_v[(size_t)i * NV + j];
                    if (offdiag)  // i != j guaranteed
                        g_adjA[(size_t)j * NV + i] = v * adj_v[(size_t)j * NV + i];
                }
            }
        }
    }
}

// ---------------- kernel 5: ret = adjA @ HW + bias (pipelined fp32 SIMT) ----------------
#define BK2 32
#define H_FLOATS (BK2 * D)           // 4096 floats (HW tile)
#define A_STRIDE 36
#define A_FLOATS (16 * A_STRIDE)     // 576 floats
#define STG2_FLOATS (H_FLOATS + A_FLOATS)   // 4672
#define NSTG2 3
#define SMEM2_BYTES (NSTG2 * STG2_FLOATS * 4)  // 56064 B

__global__ void __launch_bounds__(256, 1)
k_gemm2(const float* __restrict__ bias, float* __restrict__ out) {
    extern __shared__ float sm2[];
    uint32_t sb = smem_u32(sm2);

    int tid  = threadIdx.x;
    int warp = tid >> 5, lane = tid & 31;
    int colb = (warp & 3) * 32 + (lane & 7) * 4;
    int rowb = (warp >> 2) * 8 + (lane >> 3) * 2;
    int r0   = blockIdx.x * 16;

    const int nkt = NV / BK2;  // 64

    auto load_stage = [&](int s, int kt) {
        uint32_t base = sb + (uint32_t)(s * STG2_FLOATS) * 4u;
#pragma unroll
        for (int i = 0; i < 4; i++) {
            int c = i * 256 + tid;
            int row = c >> 5, cic = c & 31;
            cp_async16(base + (uint32_t)(row * D + cic * 4) * 4u,
                       g_HW + (size_t)(kt * BK2 + row) * D + cic * 4);
        }
        if (tid < 128) {
            int row = tid >> 3, cic = tid & 7;
            cp_async16(base + (uint32_t)(H_FLOATS + row * A_STRIDE + cic * 4) * 4u,
                       g_adjA + (size_t)(r0 + row) * NV + kt * BK2 + cic * 4);
        }
        cp_commit();
    };

    load_stage(0, 0);
    load_stage(1, 1);

    float4 acc0 = {0.f, 0.f, 0.f, 0.f};
    float4 acc1 = {0.f, 0.f, 0.f, 0.f};

    for (int kt = 0; kt < nkt; kt++) {
        if (kt + 1 < nkt) cp_wait1(); else cp_wait0();
        __syncthreads();
        int s = kt % NSTG2;
        if (kt + 2 < nkt) load_stage((kt + 2) % NSTG2, kt + 2);

        const float* sH = sm2 + s * STG2_FLOATS;
        const float* sA = sH + H_FLOATS;
        const float* a0p = sA + rowb * A_STRIDE;
        const float* a1p = a0p + A_STRIDE;

#pragma unroll
        for (int k4 = 0; k4 < BK2 / 4; k4++) {
            float4 a0 = *reinterpret_cast<const float4*>(a0p + k4 * 4);
            float4 a1 = *reinterpret_cast<const float4*>(a1p + k4 * 4);
#pragma unroll
            for (int kk = 0; kk < 4; kk++) {
                float4 h = *reinterpret_cast<const float4*>(sH + (k4 * 4 + kk) * D + colb);
                float av0 = (kk == 0) ? a0.x : (kk == 1) ? a0.y : (kk == 2) ? a0.z : a0.w;
                float av1 = (kk == 0) ? a1.x : (kk == 1) ? a1.y : (kk == 2) ? a1.z : a1.w;
                acc0.x += av0 * h.x; acc0.y += av0 * h.y;
                acc0.z += av0 * h.z; acc0.w += av0 * h.w;
                acc1.x += av1 * h.x; acc1.y += av1 * h.y;
                acc1.z += av1 * h.z; acc1.w += av1 * h.w;
            }
        }
    }

    float4 b = *reinterpret_cast<const float4*>(bias + colb);
    acc0.x += b.x; acc0.y += b.y; acc0.z += b.z; acc0.w += b.w;
    acc1.x += b.x; acc1.y += b.y; acc1.z += b.z; acc1.w += b.w;
    *reinterpret_cast<float4*>(out + (size_t)(r0 + rowb) * D + colb)     = acc0;
    *reinterpret_cast<float4*>(out + (size_t)(r0 + rowb + 1) * D + colb) = acc1;
}

// ---------------- launch ----------------
extern "C" void kernel_launch(void* const* d_in, const int* in_sizes, int n_in,
                              void* d_out, int out_size) {
    const float* H_v   = (const float*)d_in[0];
    const float* H_e   = (const float*)d_in[1];
    // d_in[2] = adj_e : UNUSED by the reference graph (node_layer branch)
    const float* adj_v = (const float*)d_in[3];
    const float* T     = (const float*)d_in[4];
    const float* W     = (const float*)d_in[5];
    const float* p     = (const float*)d_in[6];
    const float* bias  = (const float*)d_in[7];
    float* out = (float*)d_out;

    k_w<<<NE / 8, 256>>>(H_e, p);
    k_prep<<<2048, 256>>>(T);
    k_hw<<<NV / 8, 128>>>(H_v, W);

    cudaFuncSetAttribute(k_gemm1, cudaFuncAttributeMaxDynamicSharedMemorySize, SMEM_BYTES);
    k_gemm1<<<136, 512, SMEM_BYTES>>>(adj_v);

    cudaFuncSetAttribute(k_gemm2, cudaFuncAttributeMaxDynamicSharedMemorySize, SMEM2_BYTES);
    k_gemm2<<<NV / 16, 256, SMEM2_BYTES>>>(bias, out);

    // second output: H_e passthrough, concatenated after ret
    if (out_size >= NV * D + NE * D) {
        cudaMemcpyAsync(out + NV * D, H_e, (size_t)NE * D * sizeof(float),
                        cudaMemcpyDeviceToDevice, 0);
    }
}

// round 14
// speedup vs baseline: 2.3523x; 1.1836x over previous
#include <cuda_runtime.h>
#include <cuda_fp16.h>
#include <cuda_bf16.h>
#include <cstdint>

#define NV 2048
#define NE 8192
#define D  128

// ---------------- device scratch (static: no runtime allocation) ----------------
__device__ __align__(16) float g_w[NE];                          // 32 KB
__device__ __align__(16) __half g_A[(size_t)NV * NE];            // 32 MB  fp16(T*w)
__device__ __align__(16) __half g_B[(size_t)NV * NE];            // 32 MB  fp16(T)
__device__ __align__(16) __nv_bfloat16 g_adjAh[(size_t)NV * NV]; // 8 MB   hi(adjA)
__device__ __align__(16) __nv_bfloat16 g_adjAl[(size_t)NV * NV]; // 8 MB   lo(adjA)
__device__ __align__(16) __nv_bfloat16 g_HWh[(size_t)D * NV];    // 0.5 MB hi(HW^T) [j][k]
__device__ __align__(16) __nv_bfloat16 g_HWl[(size_t)D * NV];    // 0.5 MB lo(HW^T)
__device__ __align__(16) float g_part[(size_t)8 * NV * D];       // 8 MB   gemm2 partials

// ---------------- helpers ----------------
__device__ __forceinline__ void mma_fp16(float* d, const uint32_t* a, const uint32_t* b) {
    asm volatile(
        "mma.sync.aligned.m16n8k16.row.col.f32.f16.f16.f32 "
        "{%0,%1,%2,%3}, {%4,%5,%6,%7}, {%8,%9}, {%0,%1,%2,%3};\n"
        : "+f"(d[0]), "+f"(d[1]), "+f"(d[2]), "+f"(d[3])
        : "r"(a[0]), "r"(a[1]), "r"(a[2]), "r"(a[3]), "r"(b[0]), "r"(b[1]));
}

__device__ __forceinline__ void mma_bf16(float* d, const uint32_t* a, const uint32_t* b) {
    asm volatile(
        "mma.sync.aligned.m16n8k16.row.col.f32.bf16.bf16.f32 "
        "{%0,%1,%2,%3}, {%4,%5,%6,%7}, {%8,%9}, {%0,%1,%2,%3};\n"
        : "+f"(d[0]), "+f"(d[1]), "+f"(d[2]), "+f"(d[3])
        : "r"(a[0]), "r"(a[1]), "r"(a[2]), "r"(a[3]), "r"(b[0]), "r"(b[1]));
}

__device__ __forceinline__ void ldsm4(uint32_t* r, uint32_t saddr) {
    asm volatile("ldmatrix.sync.aligned.m8n8.x4.shared.b16 {%0,%1,%2,%3}, [%4];"
                 : "=r"(r[0]), "=r"(r[1]), "=r"(r[2]), "=r"(r[3]) : "r"(saddr));
}

__device__ __forceinline__ void cp_async16(uint32_t saddr, const void* g) {
    asm volatile("cp.async.cg.shared.global [%0], [%1], 16;\n" :: "r"(saddr), "l"(g));
}
__device__ __forceinline__ void cp_commit() { asm volatile("cp.async.commit_group;\n" ::: "memory"); }
__device__ __forceinline__ void cp_wait1()  { asm volatile("cp.async.wait_group 1;\n" ::: "memory"); }
__device__ __forceinline__ void cp_wait0()  { asm volatile("cp.async.wait_group 0;\n" ::: "memory"); }

__device__ __forceinline__ uint32_t smem_u32(const void* p) {
    uint32_t a;
    asm("{ .reg .u64 t; cvta.to.shared.u64 t, %1; cvt.u32.u64 %0, t; }" : "=r"(a) : "l"(p));
    return a;
}

__device__ __forceinline__ void gbar(int id) {
    asm volatile("bar.sync %0, %1;" :: "r"(id), "r"(256) : "memory");
}

__device__ __forceinline__ uint32_t pkh(__half a, __half b) {
    return (uint32_t)__half_as_ushort(a) | ((uint32_t)__half_as_ushort(b) << 16);
}
__device__ __forceinline__ uint32_t pkbf(__nv_bfloat16 a, __nv_bfloat16 b) {
    return (uint32_t)__bfloat16_as_ushort(a) | ((uint32_t)__bfloat16_as_ushort(b) << 16);
}
__device__ __forceinline__ void bfsplit(float v, __nv_bfloat16& h, __nv_bfloat16& l) {
    h = __float2bfloat16_rn(v);
    l = __float2bfloat16_rn(v - __bfloat162float(h));
}

// ---------------- kernel 1: w = H_e @ p  (warp per row) ----------------
__global__ void k_w(const float* __restrict__ He, const float* __restrict__ p) {
    int row  = blockIdx.x * 8 + (threadIdx.x >> 5);
    int lane = threadIdx.x & 31;
    const float* r = He + (size_t)row * D;
    float s = 0.f;
#pragma unroll
    for (int j = 0; j < 4; j++) {
        int k = lane + 32 * j;
        s += r[k] * __ldg(p + k);
    }
#pragma unroll
    for (int o = 16; o > 0; o >>= 1) s += __shfl_xor_sync(0xffffffffu, s, o);
    if (lane == 0) g_w[row] = s;
}

// ---------------- kernel 2: A = fp16(T*w), B = fp16(T)  (one read of T) ----------------
__global__ void __launch_bounds__(256)
k_prep(const float* __restrict__ T) {
    const size_t stride = (size_t)gridDim.x * blockDim.x;   // 524288
    size_t c = (size_t)blockIdx.x * blockDim.x + threadIdx.x;
#pragma unroll
    for (int it = 0; it < 8; it++, c += stride) {
        size_t e  = c * 4;
        int col = (int)(e & (size_t)(NE - 1));
        float4 t = *reinterpret_cast<const float4*>(T + e);
        float4 w = *reinterpret_cast<const float4*>(g_w + col);
        __half a0 = __float2half_rn(t.x * w.x), a1 = __float2half_rn(t.y * w.y);
        __half a2 = __float2half_rn(t.z * w.z), a3 = __float2half_rn(t.w * w.w);
        __half b0 = __float2half_rn(t.x), b1 = __float2half_rn(t.y);
        __half b2 = __float2half_rn(t.z), b3 = __float2half_rn(t.w);
        *reinterpret_cast<uint2*>(g_A + e) = make_uint2(pkh(a0, a1), pkh(a2, a3));
        *reinterpret_cast<uint2*>(g_B + e) = make_uint2(pkh(b0, b1), pkh(b2, b3));
    }
}

// ---------------- kernel 3: HW^T (bf16 hi/lo planes) = (H_v @ weight)^T ----------------
__global__ void k_hw(const float* __restrict__ Hv, const float* __restrict__ W) {
    __shared__ float sh[8][D];
    int r0  = blockIdx.x * 8;
    int tid = threadIdx.x;  // 128 (= output column j)
#pragma unroll
    for (int r = 0; r < 8; r++) sh[r][tid] = Hv[(size_t)(r0 + r) * D + tid];
    __syncthreads();
    float acc[8] = {};
    for (int k = 0; k < D; k++) {
        float wk = W[k * D + tid];
#pragma unroll
        for (int r = 0; r < 8; r++) acc[r] += sh[r][k] * wk;
    }
    __nv_bfloat16 h[8], l[8];
#pragma unroll
    for (int r = 0; r < 8; r++) bfsplit(acc[r], h[r], l[r]);
    uint4 ph = make_uint4(pkbf(h[0], h[1]), pkbf(h[2], h[3]), pkbf(h[4], h[5]), pkbf(h[6], h[7]));
    uint4 pl = make_uint4(pkbf(l[0], l[1]), pkbf(l[2], l[3]), pkbf(l[4], l[5]), pkbf(l[6], l[7]));
    *reinterpret_cast<uint4*>(g_HWh + (size_t)tid * NV + r0) = ph;
    *reinterpret_cast<uint4*>(g_HWl + (size_t)tid * NV + r0) = pl;
}

// ---------------- kernel 4: symmetric GEMM, fp16 m16n8k16, 2 pipelines ----
// C = fp16(T*w) @ fp16(T)^T  (2048x2048, K=8192), upper-tri 128x128 blocks.
// Two 8-warp groups (4x2 grid of 32x64 tiles), each K-half, own cp.async
// ring + named barriers. SMEM row = 64 halfs = 128B, SW128 XOR swizzle.
// Epilogue: mask + adj_v, written as bf16 hi/lo planes for the tensor gemm2.
#define BM 128
#define BK 64
#define TILE_B 16384                       // 128 rows x 128B
#define STAGE_BYTES (2 * TILE_B)           // A + B = 32KB
#define NSTAGE 3
#define GROUP_BYTES (NSTAGE * STAGE_BYTES) // 98304
#define SMEM_BYTES (2 * GROUP_BYTES)       // 196608
#define CSTRIDE 132

__global__ void __launch_bounds__(512, 1)
k_gemm1(const float* __restrict__ adj_v) {
    int l = blockIdx.x, bm = 0, rem = 16;
    while (l >= rem) { l -= rem; bm++; rem--; }
    int bn = bm + l;

    extern __shared__ float smem[];
    uint32_t sbase = smem_u32(smem);

    int tid  = threadIdx.x;
    int warp = tid >> 5, lane = tid & 31;
    int grp  = warp >> 3;
    int gtid = tid & 255;
    int w8   = warp & 7;
    int wm = w8 & 3, wn = w8 >> 2;
    int gid = lane >> 2, tig = lane & 3;

    const __half* gA = g_A + (size_t)(bm * BM) * NE + grp * (NE / 2);
    const __half* gB = g_B + (size_t)(bn * BM) * NE + grp * (NE / 2);
    uint32_t gbase = sbase + (uint32_t)grp * GROUP_BYTES;
    int bar = grp + 1;

    float acc[2][8][4];
#pragma unroll
    for (int m = 0; m < 2; m++)
#pragma unroll
        for (int n = 0; n < 8; n++)
#pragma unroll
            for (int q = 0; q < 4; q++) acc[m][n][q] = 0.f;

    const int nkt = (NE / 2) / BK;  // 32

    auto load_stage = [&](int s, int kt) {
        uint32_t base = gbase + (uint32_t)s * STAGE_BYTES;
        int cc = gtid & 7;
#pragma unroll
        for (int i = 0; i < 8; i++) {
            int c = i * 256 + gtid;
            int operand = c >> 10;
            int row = (c >> 3) & 127;
            uint32_t off = (uint32_t)(operand * TILE_B + row * 128 + cc * 16);
            uint32_t sw  = off ^ ((off >> 3) & 0x70);
            const __half* src = (operand ? gB : gA)
                              + (size_t)row * NE + kt * BK + cc * 8;
            cp_async16(base + sw, src);
        }
        cp_commit();
    };

    load_stage(0, 0);
    load_stage(1, 1);

    uint32_t xmask = (uint32_t)(lane & 7) << 4;
    uint32_t aoff[2], boff[4];
#pragma unroll
    for (int m = 0; m < 2; m++) {
        int rowA = wm * 32 + m * 16 + (lane & 7) + ((lane >> 3) & 1) * 8;
        aoff[m] = (uint32_t)(rowA * 128 + ((lane >> 4) & 1) * 16);
    }
#pragma unroll
    for (int j = 0; j < 4; j++) {
        int rowB = wn * 64 + j * 16 + (lane & 7) + ((lane >> 3) & 1) * 8;
        boff[j] = (uint32_t)(TILE_B + rowB * 128 + ((lane >> 4) & 1) * 16);
    }

    for (int kt = 0; kt < nkt; kt++) {
        if (kt + 1 < nkt) cp_wait1(); else cp_wait0();
        gbar(bar);
        int s = kt % NSTAGE;
        if (kt + 2 < nkt) load_stage((kt + 2) % NSTAGE, kt + 2);

        uint32_t stb = gbase + (uint32_t)s * STAGE_BYTES;

#pragma unroll
        for (int ks = 0; ks < 4; ks++) {
            uint32_t kb = (uint32_t)(ks * 32);
            uint32_t af[2][4], bf[8][2];
#pragma unroll
            for (int m = 0; m < 2; m++)
                ldsm4(af[m], stb + ((aoff[m] + kb) ^ xmask));
#pragma unroll
            for (int j = 0; j < 4; j++) {
                uint32_t r[4];
                ldsm4(r, stb + ((boff[j] + kb) ^ xmask));
                bf[2 * j][0]     = r[0];
                bf[2 * j + 1][0] = r[1];
                bf[2 * j][1]     = r[2];
                bf[2 * j + 1][1] = r[3];
            }
#pragma unroll
            for (int m = 0; m < 2; m++)
#pragma unroll
                for (int n = 0; n < 8; n++) mma_fp16(acc[m][n], af[m], bf[n]);
        }
        // no trailing barrier needed: the stage reloaded next iteration was
        // fully consumed before every thread arrived at THIS iteration's gbar.
    }

    // ---- combine group partials through smem, then masked bf16-split epilogue ----
    __syncthreads();
    float* cbuf = smem + GROUP_BYTES / 4;
    if (grp == 1) {
#pragma unroll
        for (int m = 0; m < 2; m++) {
            int il = wm * 32 + m * 16 + gid;
#pragma unroll
            for (int n = 0; n < 8; n++) {
                int jl = wn * 64 + n * 8 + 2 * tig;
#pragma unroll
                for (int q = 0; q < 4; q++)
                    cbuf[(il + (q >> 1) * 8) * CSTRIDE + jl + (q & 1)] = acc[m][n][q];
            }
        }
    }
    __syncthreads();

    if (grp == 0) {
        bool offdiag = (bm != bn);
#pragma unroll
        for (int m = 0; m < 2; m++) {
            int il0 = wm * 32 + m * 16 + gid;
#pragma unroll
            for (int n = 0; n < 8; n++) {
                int jl0 = wn * 64 + n * 8 + 2 * tig;
#pragma unroll
                for (int qp = 0; qp < 2; qp++) {
                    int il = il0 + qp * 8;
                    int i  = bm * BM + il;
                    int j0 = bn * BM + jl0;
                    float v0 = acc[m][n][qp * 2 + 0] + cbuf[il * CSTRIDE + jl0];
                    float v1 = acc[m][n][qp * 2 + 1] + cbuf[il * CSTRIDE + jl0 + 1];
                    float a0 = ((i == j0)     ? 1.0f : v0) * adj_v[(size_t)i * NV + j0];
                    float a1 = ((i == j0 + 1) ? 1.0f : v1) * adj_v[(size_t)i * NV + j0 + 1];
                    __nv_bfloat16 h0, l0, h1, l1;
                    bfsplit(a0, h0, l0);
                    bfsplit(a1, h1, l1);
                    *reinterpret_cast<uint32_t*>(g_adjAh + (size_t)i * NV + j0) = pkbf(h0, h1);
                    *reinterpret_cast<uint32_t*>(g_adjAl + (size_t)i * NV + j0) = pkbf(l0, l1);
                    if (offdiag) {  // mirror: i != j guaranteed
                        float w0 = v0 * adj_v[(size_t)j0 * NV + i];
                        float w1 = v1 * adj_v[(size_t)(j0 + 1) * NV + i];
                        __nv_bfloat16 mh0, ml0, mh1, ml1;
                        bfsplit(w0, mh0, ml0);
                        bfsplit(w1, mh1, ml1);
                        g_adjAh[(size_t)j0 * NV + i]       = mh0;
                        g_adjAl[(size_t)j0 * NV + i]       = ml0;
                        g_adjAh[(size_t)(j0 + 1) * NV + i] = mh1;
                        g_adjAl[(size_t)(j0 + 1) * NV + i] = ml1;
                    }
                }
            }
        }
    }
}

// ---------------- kernel 5: gemm2 partials = adjA @ HW, bf16 hi/lo tensor ----
// 128 CTAs = 16 M-blocks x 8 K-splits (K-chunk 256). 8 warps, 4x2 grid of
// 32x64 tiles. 3 MMAs per k16: AhBh + AhBl + AlBh (R11-proven split).
// Stage = [Ah|Al|Bh|Bl] x 16KB = 64KB; 3 stages.
#define STAGE2B 65536
#define SMEM2_BYTES (3 * STAGE2B)   // 196608

__global__ void __launch_bounds__(256, 1)
k_gemm2p() {
    int mb = blockIdx.x >> 3;   // 0..15
    int kc = blockIdx.x & 7;    // 0..7

    extern __shared__ float sm2[];
    uint32_t sb = smem_u32(sm2);

    int tid  = threadIdx.x;
    int warp = tid >> 5, lane = tid & 31;
    int wm = warp & 3, wn = warp >> 2;
    int gid = lane >> 2, tig = lane & 3;

    float acc[2][8][4];
#pragma unroll
    for (int m = 0; m < 2; m++)
#pragma unroll
        for (int n = 0; n < 8; n++)
#pragma unroll
            for (int q = 0; q < 4; q++) acc[m][n][q] = 0.f;

    const int nkt = 4;   // K-chunk 256 / BK 64

    auto load_stage = [&](int s, int kt) {
        uint32_t base = sb + (uint32_t)s * STAGE2B;
        int cc = tid & 7, r8 = tid >> 3;   // r8 in 0..31
        size_t kbase = (size_t)(kc * 256 + kt * 64 + cc * 8);
#pragma unroll
        for (int tile = 0; tile < 4; tile++) {
            const __nv_bfloat16* base_p =
                (tile == 0) ? g_adjAh + (size_t)(mb * 128) * NV :
                (tile == 1) ? g_adjAl + (size_t)(mb * 128) * NV :
                (tile == 2) ? g_HWh : g_HWl;
#pragma unroll
            for (int rr = 0; rr < 4; rr++) {
                int row = rr * 32 + r8;
                uint32_t off = (uint32_t)(tile * 16384 + row * 128 + cc * 16);
                uint32_t sw  = off ^ ((off >> 3) & 0x70);
                cp_async16(base + sw, base_p + (size_t)row * NV + kbase);
            }
        }
        cp_commit();
    };

    load_stage(0, 0);
    load_stage(1, 1);

    uint32_t xmask = (uint32_t)(lane & 7) << 4;
    uint32_t aoff[2][2], boff[4][2];
#pragma unroll
    for (int m = 0; m < 2; m++) {
        int rowA = wm * 32 + m * 16 + (lane & 7) + ((lane >> 3) & 1) * 8;
#pragma unroll
        for (int p = 0; p < 2; p++)
            aoff[m][p] = (uint32_t)(p * 16384 + rowA * 128 + ((lane >> 4) & 1) * 16);
    }
#pragma unroll
    for (int j = 0; j < 4; j++) {
        int rowB = wn * 64 + j * 16 + (lane & 7) + ((lane >> 3) & 1) * 8;
#pragma unroll
        for (int p = 0; p < 2; p++)
            boff[j][p] = (uint32_t)(32768 + p * 16384 + rowB * 128 + ((lane >> 4) & 1) * 16);
    }

    for (int kt = 0; kt < nkt; kt++) {
        if (kt + 1 < nkt) cp_wait1(); else cp_wait0();
        __syncthreads();
        int s = kt % 3;
        if (kt + 2 < nkt) load_stage((kt + 2) % 3, kt + 2);

        uint32_t stb = sb + (uint32_t)s * STAGE2B;

#pragma unroll
        for (int ks = 0; ks < 4; ks++) {
            uint32_t kb = (uint32_t)(ks * 32);
            uint32_t af[2][2][4];            // [m][plane]
#pragma unroll
            for (int m = 0; m < 2; m++)
#pragma unroll
                for (int p = 0; p < 2; p++)
                    ldsm4(af[m][p], stb + ((aoff[m][p] + kb) ^ xmask));

#pragma unroll
            for (int h = 0; h < 2; h++) {
                uint32_t bh[4][2], bl[4][2];   // 4 local n-tiles, 2 regs each
#pragma unroll
                for (int j = 0; j < 2; j++) {
                    uint32_t rh[4], rl[4];
                    ldsm4(rh, stb + ((boff[2 * h + j][0] + kb) ^ xmask));
                    ldsm4(rl, stb + ((boff[2 * h + j][1] + kb) ^ xmask));
                    bh[2 * j][0] = rh[0]; bh[2 * j + 1][0] = rh[1];
                    bh[2 * j][1] = rh[2]; bh[2 * j + 1][1] = rh[3];
                    bl[2 * j][0] = rl[0]; bl[2 * j + 1][0] = rl[1];
                    bl[2 * j][1] = rl[2]; bl[2 * j + 1][1] = rl[3];
                }
#pragma unroll
                for (int m = 0; m < 2; m++)
#pragma unroll
                    for (int nt = 0; nt < 4; nt++) {
                        int n = 4 * h + nt;
                        mma_bf16(acc[m][n], af[m][0], bh[nt]);  // hi*hi
                        mma_bf16(acc[m][n], af[m][0], bl[nt]);  // hi*lo
                        mma_bf16(acc[m][n], af[m][1], bh[nt]);  // lo*hi
                    }
            }
        }
    }

    // store fp32 partial block
    float* dst = g_part + (size_t)kc * NV * D + (size_t)(mb * 128) * D;
#pragma unroll
    for (int m = 0; m < 2; m++) {
        int il0 = wm * 32 + m * 16 + gid;
#pragma unroll
        for (int n = 0; n < 8; n++) {
            int jl = wn * 64 + n * 8 + 2 * tig;
#pragma unroll
            for (int qp = 0; qp < 2; qp++) {
                int il = il0 + qp * 8;
                float2 v = make_float2(acc[m][n][qp * 2], acc[m][n][qp * 2 + 1]);
                *reinterpret_cast<float2*>(dst + (size_t)il * D + jl) = v;
            }
        }
    }
}

// ---------------- kernel 6: out = sum(partials) + bias ----------------
__global__ void __launch_bounds__(256)
k_red(const float* __restrict__ bias, float* __restrict__ out) {
    int idx = blockIdx.x * 256 + threadIdx.x;     // 65536 float4s
    size_t e = (size_t)idx * 4;
    int j = (int)(e & (D - 1));
    float4 a = *reinterpret_cast<const float4*>(bias + j);
#pragma unroll
    for (int kc = 0; kc < 8; kc++) {
        float4 p = *reinterpret_cast<const float4*>(g_part + (size_t)kc * NV * D + e);
        a.x += p.x; a.y += p.y; a.z += p.z; a.w += p.w;
    }
    *reinterpret_cast<float4*>(out + e) = a;
}

// ---------------- launch ----------------
extern "C" void kernel_launch(void* const* d_in, const int* in_sizes, int n_in,
                              void* d_out, int out_size) {
    const float* H_v   = (const float*)d_in[0];
    const float* H_e   = (const float*)d_in[1];
    // d_in[2] = adj_e : UNUSED by the reference graph (node_layer branch)
    const float* adj_v = (const float*)d_in[3];
    const float* T     = (const float*)d_in[4];
    const float* W     = (const float*)d_in[5];
    const float* p     = (const float*)d_in[6];
    const float* bias  = (const float*)d_in[7];
    float* out = (float*)d_out;

    k_w<<<NE / 8, 256>>>(H_e, p);
    k_prep<<<2048, 256>>>(T);
    k_hw<<<NV / 8, 128>>>(H_v, W);

    cudaFuncSetAttribute(k_gemm1, cudaFuncAttributeMaxDynamicSharedMemorySize, SMEM_BYTES);
    k_gemm1<<<136, 512, SMEM_BYTES>>>(adj_v);

    cudaFuncSetAttribute(k_gemm2p, cudaFuncAttributeMaxDynamicSharedMemorySize, SMEM2_BYTES);
    k_gemm2p<<<128, 256, SMEM2_BYTES>>>();

    k_red<<<256, 256>>>(bias, out);

    // second output: H_e passthrough, concatenated after ret
    if (out_size >= NV * D + NE * D) {
        cudaMemcpyAsync(out + NV * D, H_e, (size_t)NE * D * sizeof(float),
                        cudaMemcpyDeviceToDevice, 0);
    }
}

// round 15
// speedup vs baseline: 2.4227x; 1.0299x over previous
#include <cuda_runtime.h>
#include <cuda_fp16.h>
#include <cuda_bf16.h>
#include <cstdint>

#define NV 2048
#define NE 8192
#define D  128

// ---------------- device scratch (static: no runtime allocation) ----------------
__device__ __align__(16) float g_w[NE];                          // 32 KB
__device__ __align__(16) __half g_A[(size_t)NV * NE];            // 32 MB  fp16(T*w)
__device__ __align__(16) __half g_B[(size_t)NV * NE];            // 32 MB  fp16(T)
__device__ __align__(16) __nv_bfloat16 g_adjAh[(size_t)NV * NV]; // 8 MB   hi(adjA)
__device__ __align__(16) __nv_bfloat16 g_adjAl[(size_t)NV * NV]; // 8 MB   lo(adjA)
__device__ __align__(16) __nv_bfloat16 g_HWh[(size_t)D * NV];    // 0.5 MB hi(HW^T) [j][k]
__device__ __align__(16) __nv_bfloat16 g_HWl[(size_t)D * NV];    // 0.5 MB lo(HW^T)
__device__ __align__(16) float g_part[(size_t)8 * NV * D];       // 8 MB   gemm2 partials

// ---------------- helpers ----------------
__device__ __forceinline__ void mma_fp16(float* d, const uint32_t* a, const uint32_t* b) {
    asm volatile(
        "mma.sync.aligned.m16n8k16.row.col.f32.f16.f16.f32 "
        "{%0,%1,%2,%3}, {%4,%5,%6,%7}, {%8,%9}, {%0,%1,%2,%3};\n"
        : "+f"(d[0]), "+f"(d[1]), "+f"(d[2]), "+f"(d[3])
        : "r"(a[0]), "r"(a[1]), "r"(a[2]), "r"(a[3]), "r"(b[0]), "r"(b[1]));
}

__device__ __forceinline__ void mma_bf16(float* d, const uint32_t* a, const uint32_t* b) {
    asm volatile(
        "mma.sync.aligned.m16n8k16.row.col.f32.bf16.bf16.f32 "
        "{%0,%1,%2,%3}, {%4,%5,%6,%7}, {%8,%9}, {%0,%1,%2,%3};\n"
        : "+f"(d[0]), "+f"(d[1]), "+f"(d[2]), "+f"(d[3])
        : "r"(a[0]), "r"(a[1]), "r"(a[2]), "r"(a[3]), "r"(b[0]), "r"(b[1]));
}

__device__ __forceinline__ void ldsm4(uint32_t* r, uint32_t saddr) {
    asm volatile("ldmatrix.sync.aligned.m8n8.x4.shared.b16 {%0,%1,%2,%3}, [%4];"
                 : "=r"(r[0]), "=r"(r[1]), "=r"(r[2]), "=r"(r[3]) : "r"(saddr));
}

__device__ __forceinline__ void cp_async16(uint32_t saddr, const void* g) {
    asm volatile("cp.async.cg.shared.global [%0], [%1], 16;\n" :: "r"(saddr), "l"(g));
}
__device__ __forceinline__ void cp_commit() { asm volatile("cp.async.commit_group;\n" ::: "memory"); }
__device__ __forceinline__ void cp_wait1()  { asm volatile("cp.async.wait_group 1;\n" ::: "memory"); }
__device__ __forceinline__ void cp_wait0()  { asm volatile("cp.async.wait_group 0;\n" ::: "memory"); }

__device__ __forceinline__ uint32_t smem_u32(const void* p) {
    uint32_t a;
    asm("{ .reg .u64 t; cvta.to.shared.u64 t, %1; cvt.u32.u64 %0, t; }" : "=r"(a) : "l"(p));
    return a;
}

__device__ __forceinline__ void gbar(int id) {
    asm volatile("bar.sync %0, %1;" :: "r"(id), "r"(256) : "memory");
}

__device__ __forceinline__ uint32_t pkh(__half a, __half b) {
    return (uint32_t)__half_as_ushort(a) | ((uint32_t)__half_as_ushort(b) << 16);
}
__device__ __forceinline__ uint32_t pkbf(__nv_bfloat16 a, __nv_bfloat16 b) {
    return (uint32_t)__bfloat16_as_ushort(a) | ((uint32_t)__bfloat16_as_ushort(b) << 16);
}
__device__ __forceinline__ void bfsplit(float v, __nv_bfloat16& h, __nv_bfloat16& l) {
    h = __float2bfloat16_rn(v);
    l = __float2bfloat16_rn(v - __bfloat162float(h));
}

// ---------------- kernel 1: w = H_e @ p  (warp per row) ----------------
__global__ void k_w(const float* __restrict__ He, const float* __restrict__ p) {
    int row  = blockIdx.x * 8 + (threadIdx.x >> 5);
    int lane = threadIdx.x & 31;
    const float* r = He + (size_t)row * D;
    float s = 0.f;
#pragma unroll
    for (int j = 0; j < 4; j++) {
        int k = lane + 32 * j;
        s += r[k] * __ldg(p + k);
    }
#pragma unroll
    for (int o = 16; o > 0; o >>= 1) s += __shfl_xor_sync(0xffffffffu, s, o);
    if (lane == 0) g_w[row] = s;
}

// ---------------- kernel 2: A = fp16(T*w), B = fp16(T)  (one read of T) ----------------
__global__ void __launch_bounds__(256)
k_prep(const float* __restrict__ T) {
    const size_t stride = (size_t)gridDim.x * blockDim.x;   // 524288
    size_t c = (size_t)blockIdx.x * blockDim.x + threadIdx.x;
#pragma unroll
    for (int it = 0; it < 8; it++, c += stride) {
        size_t e  = c * 4;
        int col = (int)(e & (size_t)(NE - 1));
        float4 t = *reinterpret_cast<const float4*>(T + e);
        float4 w = *reinterpret_cast<const float4*>(g_w + col);
        __half a0 = __float2half_rn(t.x * w.x), a1 = __float2half_rn(t.y * w.y);
        __half a2 = __float2half_rn(t.z * w.z), a3 = __float2half_rn(t.w * w.w);
        __half b0 = __float2half_rn(t.x), b1 = __float2half_rn(t.y);
        __half b2 = __float2half_rn(t.z), b3 = __float2half_rn(t.w);
        *reinterpret_cast<uint2*>(g_A + e) = make_uint2(pkh(a0, a1), pkh(a2, a3));
        *reinterpret_cast<uint2*>(g_B + e) = make_uint2(pkh(b0, b1), pkh(b2, b3));
    }
}

// ---------------- kernel 3: HW^T (bf16 hi/lo planes) = (H_v @ weight)^T ----------------
__global__ void k_hw(const float* __restrict__ Hv, const float* __restrict__ W) {
    __shared__ float sh[8][D];
    int r0  = blockIdx.x * 8;
    int tid = threadIdx.x;  // 128 (= output column j)
#pragma unroll
    for (int r = 0; r < 8; r++) sh[r][tid] = Hv[(size_t)(r0 + r) * D + tid];
    __syncthreads();
    float acc[8] = {};
    for (int k = 0; k < D; k++) {
        float wk = W[k * D + tid];
#pragma unroll
        for (int r = 0; r < 8; r++) acc[r] += sh[r][k] * wk;
    }
    __nv_bfloat16 h[8], l[8];
#pragma unroll
    for (int r = 0; r < 8; r++) bfsplit(acc[r], h[r], l[r]);
    uint4 ph = make_uint4(pkbf(h[0], h[1]), pkbf(h[2], h[3]), pkbf(h[4], h[5]), pkbf(h[6], h[7]));
    uint4 pl = make_uint4(pkbf(l[0], l[1]), pkbf(l[2], l[3]), pkbf(l[4], l[5]), pkbf(l[6], l[7]));
    *reinterpret_cast<uint4*>(g_HWh + (size_t)tid * NV + r0) = ph;
    *reinterpret_cast<uint4*>(g_HWl + (size_t)tid * NV + r0) = pl;
}

// ---------------- kernel 4: symmetric GEMM, fp16 m16n8k16, 2 pipelines ----
// C = fp16(T*w) @ fp16(T)^T  (2048x2048, K=8192), upper-tri 128x128 blocks.
// Two 8-warp groups (4x2 grid of 32x64 tiles), each K-half, own cp.async
// ring + named barriers. Fragments double-buffered (A per-ks, B per-half)
// so LDSM latency hides under the MMA stream. Mirror epilogue is staged
// through smem and written COALESCED j-major.
#define BM 128
#define BK 64
#define TILE_B 16384                       // 128 rows x 128B
#define STAGE_BYTES (2 * TILE_B)           // A + B = 32KB
#define NSTAGE 3
#define GROUP_BYTES (NSTAGE * STAGE_BYTES) // 98304
#define SMEM_BYTES (2 * GROUP_BYTES)       // 196608
#define CSTRIDE 132

__global__ void __launch_bounds__(512, 1)
k_gemm1(const float* __restrict__ adj_v) {
    int l = blockIdx.x, bm = 0, rem = 16;
    while (l >= rem) { l -= rem; bm++; rem--; }
    int bn = bm + l;

    extern __shared__ float smem[];
    uint32_t sbase = smem_u32(smem);

    int tid  = threadIdx.x;
    int warp = tid >> 5, lane = tid & 31;
    int grp  = warp >> 3;
    int gtid = tid & 255;
    int w8   = warp & 7;
    int wm = w8 & 3, wn = w8 >> 2;
    int gid = lane >> 2, tig = lane & 3;

    const __half* gA = g_A + (size_t)(bm * BM) * NE + grp * (NE / 2);
    const __half* gB = g_B + (size_t)(bn * BM) * NE + grp * (NE / 2);
    uint32_t gbase = sbase + (uint32_t)grp * GROUP_BYTES;
    int bar = grp + 1;

    float acc[2][8][4];
#pragma unroll
    for (int m = 0; m < 2; m++)
#pragma unroll
        for (int n = 0; n < 8; n++)
#pragma unroll
            for (int q = 0; q < 4; q++) acc[m][n][q] = 0.f;

    const int nkt = (NE / 2) / BK;  // 32

    auto load_stage = [&](int s, int kt) {
        uint32_t base = gbase + (uint32_t)s * STAGE_BYTES;
        int cc = gtid & 7;
#pragma unroll
        for (int i = 0; i < 8; i++) {
            int c = i * 256 + gtid;
            int operand = c >> 10;
            int row = (c >> 3) & 127;
            uint32_t off = (uint32_t)(operand * TILE_B + row * 128 + cc * 16);
            uint32_t sw  = off ^ ((off >> 3) & 0x70);
            const __half* src = (operand ? gB : gA)
                              + (size_t)row * NE + kt * BK + cc * 8;
            cp_async16(base + sw, src);
        }
        cp_commit();
    };

    load_stage(0, 0);
    load_stage(1, 1);

    uint32_t xmask = (uint32_t)(lane & 7) << 4;
    uint32_t aoff[2], boff[4];
#pragma unroll
    for (int m = 0; m < 2; m++) {
        int rowA = wm * 32 + m * 16 + (lane & 7) + ((lane >> 3) & 1) * 8;
        aoff[m] = (uint32_t)(rowA * 128 + ((lane >> 4) & 1) * 16);
    }
#pragma unroll
    for (int j = 0; j < 4; j++) {
        int rowB = wn * 64 + j * 16 + (lane & 7) + ((lane >> 3) & 1) * 8;
        boff[j] = (uint32_t)(TILE_B + rowB * 128 + ((lane >> 4) & 1) * 16);
    }

    for (int kt = 0; kt < nkt; kt++) {
        if (kt + 1 < nkt) cp_wait1(); else cp_wait0();
        gbar(bar);
        int s = kt % NSTAGE;
        if (kt + 2 < nkt) load_stage((kt + 2) % NSTAGE, kt + 2);

        uint32_t stb = gbase + (uint32_t)s * STAGE_BYTES;

        uint32_t af[2][2][4];   // [buf][m]
        uint32_t bq[2][2][4];   // [buf][j-local ldsm]

        // preload ks=0 / half 0
        ldsm4(af[0][0], stb + (aoff[0] ^ xmask));
        ldsm4(af[0][1], stb + (aoff[1] ^ xmask));
        ldsm4(bq[0][0], stb + (boff[0] ^ xmask));
        ldsm4(bq[0][1], stb + (boff[1] ^ xmask));

#pragma unroll
        for (int ks = 0; ks < 4; ks++) {
            int ab = ks & 1;
#pragma unroll
            for (int h = 0; h < 2; h++) {
                int hs = ks * 2 + h;
                int bb = hs & 1;
                // prefetch next fragments while this half's MMAs drain
                if (h == 0 && ks < 3) {
                    uint32_t kb2 = (uint32_t)((ks + 1) * 32);
                    ldsm4(af[ab ^ 1][0], stb + ((aoff[0] + kb2) ^ xmask));
                    ldsm4(af[ab ^ 1][1], stb + ((aoff[1] + kb2) ^ xmask));
                }
                if (hs + 1 < 8) {
                    int ks2 = (hs + 1) >> 1, h2 = (hs + 1) & 1;
                    uint32_t kb2 = (uint32_t)(ks2 * 32);
                    ldsm4(bq[bb ^ 1][0], stb + ((boff[2 * h2] + kb2) ^ xmask));
                    ldsm4(bq[bb ^ 1][1], stb + ((boff[2 * h2 + 1] + kb2) ^ xmask));
                }
#pragma unroll
                for (int m = 0; m < 2; m++)
#pragma unroll
                    for (int nt = 0; nt < 4; nt++) {
                        int n = 4 * h + nt;
                        uint32_t bv[2] = {bq[bb][nt >> 1][nt & 1],
                                          bq[bb][nt >> 1][2 + (nt & 1)]};
                        mma_fp16(acc[m][n], af[ab][m], bv);
                    }
            }
        }
    }

    // ---- combine group partials through smem, masked epilogue, coalesced mirror ----
    __syncthreads();
    float* cbuf = smem + GROUP_BYTES / 4;   // 128 x 132 floats = 67.6 KB
    if (grp == 1) {
#pragma unroll
        for (int m = 0; m < 2; m++) {
            int il = wm * 32 + m * 16 + gid;
#pragma unroll
            for (int n = 0; n < 8; n++) {
                int jl = wn * 64 + n * 8 + 2 * tig;
#pragma unroll
                for (int q = 0; q < 4; q++)
                    cbuf[(il + (q >> 1) * 8) * CSTRIDE + jl + (q & 1)] = acc[m][n][q];
            }
        }
    }
    __syncthreads();

    bool offdiag = (bm != bn);
    if (grp == 0) {
#pragma unroll
        for (int m = 0; m < 2; m++) {
            int il0 = wm * 32 + m * 16 + gid;
#pragma unroll
            for (int n = 0; n < 8; n++) {
                int jl0 = wn * 64 + n * 8 + 2 * tig;
#pragma unroll
                for (int qp = 0; qp < 2; qp++) {
                    int il = il0 + qp * 8;
                    int i  = bm * BM + il;
                    int j0 = bn * BM + jl0;
                    float v0 = acc[m][n][qp * 2 + 0] + cbuf[il * CSTRIDE + jl0];
                    float v1 = acc[m][n][qp * 2 + 1] + cbuf[il * CSTRIDE + jl0 + 1];
                    float a0 = ((i == j0)     ? 1.0f : v0) * adj_v[(size_t)i * NV + j0];
                    float a1 = ((i == j0 + 1) ? 1.0f : v1) * adj_v[(size_t)i * NV + j0 + 1];
                    __nv_bfloat16 h0, l0, h1, l1;
                    bfsplit(a0, h0, l0);
                    bfsplit(a1, h1, l1);
                    *reinterpret_cast<uint32_t*>(g_adjAh + (size_t)i * NV + j0) = pkbf(h0, h1);
                    *reinterpret_cast<uint32_t*>(g_adjAl + (size_t)i * NV + j0) = pkbf(l0, l1);
                    // stage summed v back for the coalesced mirror pass
                    cbuf[il * CSTRIDE + jl0]     = v0;
                    cbuf[il * CSTRIDE + jl0 + 1] = v1;
                }
            }
        }
    }
    __syncthreads();

    if (offdiag) {
        // mirror block (bn,bm): write j-major, fully coalesced
#pragma unroll 4
        for (int it = 0; it < 16; it++) {
            int c  = it * 512 + tid;          // 8192 i-pairs: 128 j x 64 pairs
            int jl = c >> 6;
            int i0 = (c & 63) * 2;
            int j  = bn * BM + jl;
            size_t rowb = (size_t)j * NV + bm * BM;
            float v0 = cbuf[i0 * CSTRIDE + jl];
            float v1 = cbuf[(i0 + 1) * CSTRIDE + jl];
            float w0 = v0 * adj_v[rowb + i0];
            float w1 = v1 * adj_v[rowb + i0 + 1];
            __nv_bfloat16 h0, l0, h1, l1;
            bfsplit(w0, h0, l0);
            bfsplit(w1, h1, l1);
            *reinterpret_cast<uint32_t*>(g_adjAh + rowb + i0) = pkbf(h0, h1);
            *reinterpret_cast<uint32_t*>(g_adjAl + rowb + i0) = pkbf(l0, l1);
        }
    }
}

// ---------------- kernel 5: gemm2 partials = adjA @ HW, bf16 hi/lo tensor ----
#define STAGE2B 65536
#define SMEM2_BYTES (3 * STAGE2B)   // 196608

__global__ void __launch_bounds__(256, 1)
k_gemm2p() {
    int mb = blockIdx.x >> 3;   // 0..15
    int kc = blockIdx.x & 7;    // 0..7

    extern __shared__ float sm2[];
    uint32_t sb = smem_u32(sm2);

    int tid  = threadIdx.x;
    int warp = tid >> 5, lane = tid & 31;
    int wm = warp & 3, wn = warp >> 2;
    int gid = lane >> 2, tig = lane & 3;

    float acc[2][8][4];
#pragma unroll
    for (int m = 0; m < 2; m++)
#pragma unroll
        for (int n = 0; n < 8; n++)
#pragma unroll
            for (int q = 0; q < 4; q++) acc[m][n][q] = 0.f;

    const int nkt = 4;   // K-chunk 256 / BK 64

    auto load_stage = [&](int s, int kt) {
        uint32_t base = sb + (uint32_t)s * STAGE2B;
        int cc = tid & 7, r8 = tid >> 3;
        size_t kbase = (size_t)(kc * 256 + kt * 64 + cc * 8);
#pragma unroll
        for (int tile = 0; tile < 4; tile++) {
            const __nv_bfloat16* base_p =
                (tile == 0) ? g_adjAh + (size_t)(mb * 128) * NV :
                (tile == 1) ? g_adjAl + (size_t)(mb * 128) * NV :
                (tile == 2) ? g_HWh : g_HWl;
#pragma unroll
            for (int rr = 0; rr < 4; rr++) {
                int row = rr * 32 + r8;
                uint32_t off = (uint32_t)(tile * 16384 + row * 128 + cc * 16);
                uint32_t sw  = off ^ ((off >> 3) & 0x70);
                cp_async16(base + sw, base_p + (size_t)row * NV + kbase);
            }
        }
        cp_commit();
    };

    load_stage(0, 0);
    load_stage(1, 1);

    uint32_t xmask = (uint32_t)(lane & 7) << 4;
    uint32_t aoff[2][2], boff[4][2];
#pragma unroll
    for (int m = 0; m < 2; m++) {
        int rowA = wm * 32 + m * 16 + (lane & 7) + ((lane >> 3) & 1) * 8;
#pragma unroll
        for (int p = 0; p < 2; p++)
            aoff[m][p] = (uint32_t)(p * 16384 + rowA * 128 + ((lane >> 4) & 1) * 16);
    }
#pragma unroll
    for (int j = 0; j < 4; j++) {
        int rowB = wn * 64 + j * 16 + (lane & 7) + ((lane >> 3) & 1) * 8;
#pragma unroll
        for (int p = 0; p < 2; p++)
            boff[j][p] = (uint32_t)(32768 + p * 16384 + rowB * 128 + ((lane >> 4) & 1) * 16);
    }

    for (int kt = 0; kt < nkt; kt++) {
        if (kt + 1 < nkt) cp_wait1(); else cp_wait0();
        __syncthreads();
        int s = kt % 3;
        if (kt + 2 < nkt) load_stage((kt + 2) % 3, kt + 2);

        uint32_t stb = sb + (uint32_t)s * STAGE2B;

#pragma unroll
        for (int ks = 0; ks < 4; ks++) {
            uint32_t kb = (uint32_t)(ks * 32);
            uint32_t af[2][2][4];
#pragma unroll
            for (int m = 0; m < 2; m++)
#pragma unroll
                for (int p = 0; p < 2; p++)
                    ldsm4(af[m][p], stb + ((aoff[m][p] + kb) ^ xmask));

#pragma unroll
            for (int h = 0; h < 2; h++) {
                uint32_t bh[4][2], bl[4][2];
#pragma unroll
                for (int j = 0; j < 2; j++) {
                    uint32_t rh[4], rl[4];
                    ldsm4(rh, stb + ((boff[2 * h + j][0] + kb) ^ xmask));
                    ldsm4(rl, stb + ((boff[2 * h + j][1] + kb) ^ xmask));
                    bh[2 * j][0] = rh[0]; bh[2 * j + 1][0] = rh[1];
                    bh[2 * j][1] = rh[2]; bh[2 * j + 1][1] = rh[3];
                    bl[2 * j][0] = rl[0]; bl[2 * j + 1][0] = rl[1];
                    bl[2 * j][1] = rl[2]; bl[2 * j + 1][1] = rl[3];
                }
#pragma unroll
                for (int m = 0; m < 2; m++)
#pragma unroll
                    for (int nt = 0; nt < 4; nt++) {
                        int n = 4 * h + nt;
                        mma_bf16(acc[m][n], af[m][0], bh[nt]);  // hi*hi
                        mma_bf16(acc[m][n], af[m][0], bl[nt]);  // hi*lo
                        mma_bf16(acc[m][n], af[m][1], bh[nt]);  // lo*hi
                    }
            }
        }
    }

    float* dst = g_part + (size_t)kc * NV * D + (size_t)(mb * 128) * D;
#pragma unroll
    for (int m = 0; m < 2; m++) {
        int il0 = wm * 32 + m * 16 + gid;
#pragma unroll
        for (int n = 0; n < 8; n++) {
            int jl = wn * 64 + n * 8 + 2 * tig;
#pragma unroll
            for (int qp = 0; qp < 2; qp++) {
                int il = il0 + qp * 8;
                float2 v = make_float2(acc[m][n][qp * 2], acc[m][n][qp * 2 + 1]);
                *reinterpret_cast<float2*>(dst + (size_t)il * D + jl) = v;
            }
        }
    }
}

// ---------------- kernel 6: out = sum(partials) + bias ----------------
__global__ void __launch_bounds__(256)
k_red(const float* __restrict__ bias, float* __restrict__ out) {
    int idx = blockIdx.x * 256 + threadIdx.x;     // 65536 float4s
    size_t e = (size_t)idx * 4;
    int j = (int)(e & (D - 1));
    float4 a = *reinterpret_cast<const float4*>(bias + j);
#pragma unroll
    for (int kc = 0; kc < 8; kc++) {
        float4 p = *reinterpret_cast<const float4*>(g_part + (size_t)kc * NV * D + e);
        a.x += p.x; a.y += p.y; a.z += p.z; a.w += p.w;
    }
    *reinterpret_cast<float4*>(out + e) = a;
}

// ---------------- launch ----------------
extern "C" void kernel_launch(void* const* d_in, const int* in_sizes, int n_in,
                              void* d_out, int out_size) {
    const float* H_v   = (const float*)d_in[0];
    const float* H_e   = (const float*)d_in[1];
    // d_in[2] = adj_e : UNUSED by the reference graph (node_layer branch)
    const float* adj_v = (const float*)d_in[3];
    const float* T     = (const float*)d_in[4];
    const float* W     = (const float*)d_in[5];
    const float* p     = (const float*)d_in[6];
    const float* bias  = (const float*)d_in[7];
    float* out = (float*)d_out;

    k_w<<<NE / 8, 256>>>(H_e, p);
    k_prep<<<2048, 256>>>(T);
    k_hw<<<NV / 8, 128>>>(H_v, W);

    cudaFuncSetAttribute(k_gemm1, cudaFuncAttributeMaxDynamicSharedMemorySize, SMEM_BYTES);
    k_gemm1<<<136, 512, SMEM_BYTES>>>(adj_v);

    cudaFuncSetAttribute(k_gemm2p, cudaFuncAttributeMaxDynamicSharedMemorySize, SMEM2_BYTES);
    k_gemm2p<<<128, 256, SMEM2_BYTES>>>();

    k_red<<<256, 256>>>(bias, out);

    // second output: H_e passthrough, concatenated after ret
    if (out_size >= NV * D + NE * D) {
        cudaMemcpyAsync(out + NV * D, H_e, (size_t)NE * D * sizeof(float),
                        cudaMemcpyDeviceToDevice, 0);
    }
}